// round 1
// baseline (speedup 1.0000x reference)
#include <cuda_runtime.h>
#include <math.h>

#define S_LEN 2048
#define HID   2048
#define NH    32
#define NKV   8
#define HD    64

// Scratch (device globals: allocation-free per harness rules)
__device__ float g_q[NH * S_LEN * HD];     // [h][s][d]
__device__ float g_k[NKV * S_LEN * HD];    // [h][s][d]
__device__ float g_v[NKV * S_LEN * HD];    // [h][s][d]
__device__ float g_ctx[S_LEN * NH * HD];   // [s][h*64+d]

// ---------------------------------------------------------------------------
// Tiled fp32 GEMM: C[row,c] = sum_k A[row,k] * W[c,k] (+ bias[c])
// 128x128 block tile, K-tile 8, 256 threads, 8x8 per-thread micro-tile.
// MODE 0/1/2 -> scatter into g_q/g_k/g_v in [head][s][d] layout
// MODE 3     -> A := g_ctx, plain row-major store to outp
// ---------------------------------------------------------------------------
template <int MODE>
__global__ __launch_bounds__(256) void gemm_k(const float* __restrict__ A,
                                              const float* __restrict__ W,
                                              const float* __restrict__ bias,
                                              float* __restrict__ outp)
{
    __shared__ float As[8][128];
    __shared__ float Bs[8][128];

    const int bm = blockIdx.y * 128;
    const int bn = blockIdx.x * 128;
    const int t  = threadIdx.x;
    const int tx = t & 15;
    const int ty = t >> 4;
    const int lrow = t >> 1;        // 0..127
    const int lq   = (t & 1) * 4;   // 0 or 4

    const float* Abase = (MODE == 3) ? (const float*)g_ctx : A;
    const float* Ap = Abase + (size_t)(bm + lrow) * HID;
    const float* Wp = W + (size_t)(bn + lrow) * HID;

    float acc[8][8];
#pragma unroll
    for (int i = 0; i < 8; ++i)
#pragma unroll
        for (int j = 0; j < 8; ++j) acc[i][j] = 0.0f;

    for (int k0 = 0; k0 < HID; k0 += 8) {
        float4 av = *(const float4*)(Ap + k0 + lq);
        float4 bv = *(const float4*)(Wp + k0 + lq);
        As[lq + 0][lrow] = av.x;
        As[lq + 1][lrow] = av.y;
        As[lq + 2][lrow] = av.z;
        As[lq + 3][lrow] = av.w;
        Bs[lq + 0][lrow] = bv.x;
        Bs[lq + 1][lrow] = bv.y;
        Bs[lq + 2][lrow] = bv.z;
        Bs[lq + 3][lrow] = bv.w;
        __syncthreads();

#pragma unroll
        for (int kk = 0; kk < 8; ++kk) {
            float a[8], b[8];
#pragma unroll
            for (int i = 0; i < 8; ++i) a[i] = As[kk][ty * 8 + i];
#pragma unroll
            for (int j = 0; j < 8; ++j) b[j] = Bs[kk][tx * 8 + j];
#pragma unroll
            for (int i = 0; i < 8; ++i)
#pragma unroll
                for (int j = 0; j < 8; ++j) acc[i][j] += a[i] * b[j];
        }
        __syncthreads();
    }

#pragma unroll
    for (int i = 0; i < 8; ++i) {
        const int row = bm + ty * 8 + i;
#pragma unroll
        for (int j = 0; j < 8; ++j) {
            const int c = bn + tx * 8 + j;
            float v = acc[i][j];
            if (MODE < 3) v += bias[c];
            if (MODE == 0)      g_q[(size_t)(c >> 6) * (S_LEN * HD) + (size_t)row * HD + (c & 63)] = v;
            else if (MODE == 1) g_k[(size_t)(c >> 6) * (S_LEN * HD) + (size_t)row * HD + (c & 63)] = v;
            else if (MODE == 2) g_v[(size_t)(c >> 6) * (S_LEN * HD) + (size_t)row * HD + (c & 63)] = v;
            else                outp[(size_t)row * HID + c] = v;
        }
    }
}

// ---------------------------------------------------------------------------
// RoPE in-place on g_q (WHICH=0) or g_k (WHICH=1).
// pair (j, j+32) within each head-dim of 64: standard rotate_half formulation.
// ---------------------------------------------------------------------------
template <int WHICH>
__global__ __launch_bounds__(256) void rope_k()
{
    const int nheads = (WHICH == 0) ? NH : NKV;
    const int idx = blockIdx.x * blockDim.x + threadIdx.x;
    const int total = nheads * S_LEN * 32;
    if (idx >= total) return;
    const int j = idx & 31;
    const int s = (idx >> 5) & (S_LEN - 1);
    const int h = idx >> 16;   // 2048*32 == 2^16

    const float inv_freq = powf(10000.0f, -((float)(2 * j)) / 64.0f);
    const float ang = (float)s * inv_freq;
    float sn, cs;
    sincosf(ang, &sn, &cs);

    float* p = (WHICH == 0 ? g_q : g_k) + ((size_t)h * S_LEN + s) * HD;
    const float x1 = p[j];
    const float x2 = p[j + 32];
    p[j]      = x1 * cs - x2 * sn;
    p[j + 32] = x2 * cs + x1 * sn;
}

// ---------------------------------------------------------------------------
// Flash attention (causal, clip(-50,50), scale 1/8, GQA 4 q-heads per kv-head)
// Block: one (head, 64-row q block). 256 threads, 4x4 micro-tile.
// smem: Qs[64][64] | KP[64][65] (K tile, reused as P tile) | Vs[64][65]
// ---------------------------------------------------------------------------
#define ATTN_SMEM ((64 * 64 + 2 * 64 * 65) * 4)

__global__ __launch_bounds__(256) void attn_k()
{
    const int h = blockIdx.y;
    const int zz = blockIdx.x;
    const int qb = (zz & 1) ? (31 - (zz >> 1)) : (zz >> 1);   // interleave for causal balance
    const int kvh = h >> 2;  // GROUPS = 4

    extern __shared__ float sm[];
    float* Qs = sm;                  // 64*64
    float* KP = sm + 64 * 64;        // 64*65
    float* Vs = KP + 64 * 65;        // 64*65

    const int t  = threadIdx.x;
    const int tx = t & 15;
    const int ty = t >> 4;
    const int r0 = ty * 4;
    const int c0 = tx * 4;

    // Load Q tile
    const float* Qg = g_q + ((size_t)h * S_LEN + (size_t)qb * 64) * HD;
    for (int i = t; i < 1024; i += 256) {
        const int r = i >> 4;
        const int q = (i & 15) * 4;
        *(float4*)(Qs + r * 64 + q) = *(const float4*)(Qg + r * 64 + q);
    }

    float m_i[4], l_i[4], acc[4][4];
#pragma unroll
    for (int i = 0; i < 4; ++i) {
        m_i[i] = -1e30f;
        l_i[i] = 0.0f;
#pragma unroll
        for (int j = 0; j < 4; ++j) acc[i][j] = 0.0f;
    }

    for (int kb = 0; kb <= qb; ++kb) {
        __syncthreads();  // previous P consumers done before overwriting KP
        const float* Kg = g_k + ((size_t)kvh * S_LEN + (size_t)kb * 64) * HD;
        const float* Vg = g_v + ((size_t)kvh * S_LEN + (size_t)kb * 64) * HD;
        for (int i = t; i < 1024; i += 256) {
            const int r = i >> 4;
            const int q = (i & 15) * 4;
            float4 kk = *(const float4*)(Kg + r * 64 + q);
            KP[r * 65 + q + 0] = kk.x;
            KP[r * 65 + q + 1] = kk.y;
            KP[r * 65 + q + 2] = kk.z;
            KP[r * 65 + q + 3] = kk.w;
            float4 vv = *(const float4*)(Vg + r * 64 + q);
            Vs[r * 65 + q + 0] = vv.x;
            Vs[r * 65 + q + 1] = vv.y;
            Vs[r * 65 + q + 2] = vv.z;
            Vs[r * 65 + q + 3] = vv.w;
        }
        __syncthreads();

        // S = Q K^T (4x4 per thread)
        float s[4][4];
#pragma unroll
        for (int i = 0; i < 4; ++i)
#pragma unroll
            for (int j = 0; j < 4; ++j) s[i][j] = 0.0f;

#pragma unroll 8
        for (int k = 0; k < 64; ++k) {
            float a0 = Qs[(r0 + 0) * 64 + k];
            float a1 = Qs[(r0 + 1) * 64 + k];
            float a2 = Qs[(r0 + 2) * 64 + k];
            float a3 = Qs[(r0 + 3) * 64 + k];
            float b0 = KP[(c0 + 0) * 65 + k];
            float b1 = KP[(c0 + 1) * 65 + k];
            float b2 = KP[(c0 + 2) * 65 + k];
            float b3 = KP[(c0 + 3) * 65 + k];
            s[0][0] += a0 * b0; s[0][1] += a0 * b1; s[0][2] += a0 * b2; s[0][3] += a0 * b3;
            s[1][0] += a1 * b0; s[1][1] += a1 * b1; s[1][2] += a1 * b2; s[1][3] += a1 * b3;
            s[2][0] += a2 * b0; s[2][1] += a2 * b1; s[2][2] += a2 * b2; s[2][3] += a2 * b3;
            s[3][0] += a3 * b0; s[3][1] += a3 * b1; s[3][2] += a3 * b2; s[3][3] += a3 * b3;
        }

        const bool diag = (kb == qb);
        float mt[4];
#pragma unroll
        for (int i = 0; i < 4; ++i) {
#pragma unroll
            for (int j = 0; j < 4; ++j) {
                float v = s[i][j] * 0.125f;
                v = fminf(fmaxf(v, -50.0f), 50.0f);
                if (diag && (c0 + j) > (r0 + i)) v = -1e30f;
                s[i][j] = v;
            }
            mt[i] = fmaxf(fmaxf(s[i][0], s[i][1]), fmaxf(s[i][2], s[i][3]));
        }
        // row-max across the 16 threads sharing each row group
#pragma unroll
        for (int o = 1; o < 16; o <<= 1) {
#pragma unroll
            for (int i = 0; i < 4; ++i)
                mt[i] = fmaxf(mt[i], __shfl_xor_sync(0xffffffffu, mt[i], o));
        }

        float corr[4], rs[4];
#pragma unroll
        for (int i = 0; i < 4; ++i) {
            const float mn = fmaxf(m_i[i], mt[i]);
            corr[i] = __expf(m_i[i] - mn);
            m_i[i] = mn;
            float r = 0.0f;
#pragma unroll
            for (int j = 0; j < 4; ++j) {
                const float p = __expf(s[i][j] - mn);
                s[i][j] = p;
                r += p;
            }
            rs[i] = r;
        }
#pragma unroll
        for (int o = 1; o < 16; o <<= 1) {
#pragma unroll
            for (int i = 0; i < 4; ++i)
                rs[i] += __shfl_xor_sync(0xffffffffu, rs[i], o);
        }
#pragma unroll
        for (int i = 0; i < 4; ++i) {
            l_i[i] = l_i[i] * corr[i] + rs[i];
#pragma unroll
            for (int j = 0; j < 4; ++j) acc[i][j] *= corr[i];
        }

        __syncthreads();  // all K reads done -> reuse KP for P
#pragma unroll
        for (int i = 0; i < 4; ++i)
#pragma unroll
            for (int j = 0; j < 4; ++j)
                KP[(r0 + i) * 65 + (c0 + j)] = s[i][j];
        __syncthreads();

        // O += P V
#pragma unroll 8
        for (int c = 0; c < 64; ++c) {
            float p0 = KP[(r0 + 0) * 65 + c];
            float p1 = KP[(r0 + 1) * 65 + c];
            float p2 = KP[(r0 + 2) * 65 + c];
            float p3 = KP[(r0 + 3) * 65 + c];
            float v0 = Vs[c * 65 + c0 + 0];
            float v1 = Vs[c * 65 + c0 + 1];
            float v2 = Vs[c * 65 + c0 + 2];
            float v3 = Vs[c * 65 + c0 + 3];
            acc[0][0] += p0 * v0; acc[0][1] += p0 * v1; acc[0][2] += p0 * v2; acc[0][3] += p0 * v3;
            acc[1][0] += p1 * v0; acc[1][1] += p1 * v1; acc[1][2] += p1 * v2; acc[1][3] += p1 * v3;
            acc[2][0] += p2 * v0; acc[2][1] += p2 * v1; acc[2][2] += p2 * v2; acc[2][3] += p2 * v3;
            acc[3][0] += p3 * v0; acc[3][1] += p3 * v1; acc[3][2] += p3 * v2; acc[3][3] += p3 * v3;
        }
    }

#pragma unroll
    for (int i = 0; i < 4; ++i) {
        const float inv = 1.0f / l_i[i];
        const int row = qb * 64 + r0 + i;
        float* op = g_ctx + (size_t)row * HID + h * 64 + c0;
#pragma unroll
        for (int j = 0; j < 4; ++j) op[j] = acc[i][j] * inv;
    }
}

// ---------------------------------------------------------------------------
// Launcher
// ---------------------------------------------------------------------------
extern "C" void kernel_launch(void* const* d_in, const int* in_sizes, int n_in,
                              void* d_out, int out_size)
{
    const float* X  = (const float*)d_in[0];
    // d_in[1] = attention_mask (exactly causal; implemented analytically)
    const float* Wq = (const float*)d_in[2];
    const float* bq = (const float*)d_in[3];
    const float* Wk = (const float*)d_in[4];
    const float* bk = (const float*)d_in[5];
    const float* Wv = (const float*)d_in[6];
    const float* bv = (const float*)d_in[7];
    const float* Wo = (const float*)d_in[8];
    float* out = (float*)d_out;

    // QKV projections
    gemm_k<0><<<dim3(HID / 128, S_LEN / 128), 256>>>(X, Wq, bq, nullptr);
    gemm_k<1><<<dim3((NKV * HD) / 128, S_LEN / 128), 256>>>(X, Wk, bk, nullptr);
    gemm_k<2><<<dim3((NKV * HD) / 128, S_LEN / 128), 256>>>(X, Wv, bv, nullptr);

    // RoPE
    rope_k<0><<<(NH * S_LEN * 32) / 256, 256>>>();
    rope_k<1><<<(NKV * S_LEN * 32) / 256, 256>>>();

    // Flash attention (needs >48KB dynamic smem)
    cudaFuncSetAttribute(attn_k, cudaFuncAttributeMaxDynamicSharedMemorySize, ATTN_SMEM);
    attn_k<<<dim3(32, NH), 256, ATTN_SMEM>>>();

    // Output projection
    gemm_k<3><<<dim3(HID / 128, S_LEN / 128), 256>>>(nullptr, Wo, nullptr, out);
}

// round 3
// speedup vs baseline: 1.8223x; 1.8223x over previous
#include <cuda_runtime.h>
#include <cuda_bf16.h>
#include <math.h>
#include <stdint.h>

#define S_LEN 2048
#define HID   2048
#define NH    32
#define NKV   8
#define HD    64

// ---------------------------------------------------------------------------
// Scratch (device globals: allocation-free per harness rules)
// ---------------------------------------------------------------------------
__device__ float g_q[NH * S_LEN * HD];     // [h][s][d] fp32
__device__ float g_k[NKV * S_LEN * HD];
__device__ float g_v[NKV * S_LEN * HD];

__device__ __nv_bfloat16 g_Xh[S_LEN * HID],  g_Xl[S_LEN * HID];
__device__ __nv_bfloat16 g_Wqh[HID * HID],   g_Wql[HID * HID];
__device__ __nv_bfloat16 g_Wkh[NKV*HD*HID],  g_Wkl[NKV*HD*HID];
__device__ __nv_bfloat16 g_Wvh[NKV*HD*HID],  g_Wvl[NKV*HD*HID];
__device__ __nv_bfloat16 g_Woh[HID * HID],   g_Wol[HID * HID];
__device__ __nv_bfloat16 g_Ch[S_LEN * HID],  g_Cl[S_LEN * HID];   // attn out split

// ---------------------------------------------------------------------------
// Warp MMA helpers (plain sm_80+ PTX; no 'a'-gated features)
// ---------------------------------------------------------------------------
__device__ __forceinline__ uint32_t s2u(const void* p) {
    uint32_t a;
    asm("{ .reg .u64 t; cvta.to.shared.u64 t, %1; cvt.u32.u64 %0, t; }" : "=r"(a) : "l"(p));
    return a;
}

__device__ __forceinline__ void ldsm4(uint32_t& r0, uint32_t& r1, uint32_t& r2, uint32_t& r3,
                                      uint32_t addr) {
    asm volatile("ldmatrix.sync.aligned.m8n8.x4.shared.b16 {%0,%1,%2,%3}, [%4];"
                 : "=r"(r0), "=r"(r1), "=r"(r2), "=r"(r3) : "r"(addr));
}

__device__ __forceinline__ void mma16816(float* d, uint32_t a0, uint32_t a1, uint32_t a2,
                                         uint32_t a3, uint32_t b0, uint32_t b1) {
    asm volatile(
        "mma.sync.aligned.m16n8k16.row.col.f32.bf16.bf16.f32 "
        "{%0,%1,%2,%3}, {%4,%5,%6,%7}, {%8,%9}, {%0,%1,%2,%3};"
        : "+f"(d[0]), "+f"(d[1]), "+f"(d[2]), "+f"(d[3])
        : "r"(a0), "r"(a1), "r"(a2), "r"(a3), "r"(b0), "r"(b1));
}

// ---------------------------------------------------------------------------
// fp32 -> (bf16 hi, bf16 lo) split.
// ---------------------------------------------------------------------------
__global__ __launch_bounds__(256) void split_k(const float* __restrict__ src, int which, int n4)
{
    int i = blockIdx.x * 256 + threadIdx.x;
    if (i >= n4) return;
    __nv_bfloat16 *hi, *lo;
    switch (which) {
        case 0: hi = g_Xh;  lo = g_Xl;  break;
        case 1: hi = g_Wqh; lo = g_Wql; break;
        case 2: hi = g_Wkh; lo = g_Wkl; break;
        case 3: hi = g_Wvh; lo = g_Wvl; break;
        default: hi = g_Woh; lo = g_Wol; break;
    }
    float4 v = ((const float4*)src)[i];
    __nv_bfloat16 h[4], l[4];
    float f[4] = {v.x, v.y, v.z, v.w};
#pragma unroll
    for (int k = 0; k < 4; ++k) {
        h[k] = __float2bfloat16(f[k]);
        l[k] = __float2bfloat16(f[k] - __bfloat162float(h[k]));
    }
    *(uint64_t*)(hi + 4 * i) = *(uint64_t*)h;
    *(uint64_t*)(lo + 4 * i) = *(uint64_t*)l;
}

// ---------------------------------------------------------------------------
// Split-bf16 HMMA GEMM: C[M,N] = A * B^T (+bias), fp32-accurate (3-term).
// CTA tile 128x128, K-tile 32, 8 warps (4x2 -> warp tile 32x64).
// smem rows padded to 40 halfs (80B) -> conflict-free ldmatrix.
// MODE 0/1/2 -> scatter fp32 into g_q/g_k/g_v [h][s][d]; MODE 3 -> row-major out.
// ---------------------------------------------------------------------------
template <int MODE>
__global__ __launch_bounds__(256) void hgemm_k(const float* __restrict__ bias,
                                               float* __restrict__ outp)
{
    __shared__ __align__(16) __nv_bfloat16 sm[4 * 128 * 40];   // Ah | Al | Bh | Bl

    const int t = threadIdx.x, w = t >> 5, lane = t & 31;
    const int bm = blockIdx.y * 128, bn = blockIdx.x * 128;
    const int wm = (w & 3) * 32, wn = (w >> 2) * 64;

    const __nv_bfloat16 *Ah, *Al, *Bh, *Bl;
    if (MODE == 0)      { Ah = g_Xh; Al = g_Xl; Bh = g_Wqh; Bl = g_Wql; }
    else if (MODE == 1) { Ah = g_Xh; Al = g_Xl; Bh = g_Wkh; Bl = g_Wkl; }
    else if (MODE == 2) { Ah = g_Xh; Al = g_Xl; Bh = g_Wvh; Bl = g_Wvl; }
    else                { Ah = g_Ch; Al = g_Cl; Bh = g_Woh; Bl = g_Wol; }

    const __nv_bfloat16* srcs[4] = { Ah + (size_t)bm * HID, Al + (size_t)bm * HID,
                                     Bh + (size_t)bn * HID, Bl + (size_t)bn * HID };

    const uint32_t sb = s2u(sm);
    // ldmatrix address bases (per-lane), computed once
    // A frag lanes: row = (lane&15), col8 = (lane>>4)
    const uint32_t a_r = lane & 15, a_c8 = (lane >> 4) << 3;
    // B frag lanes: row = ((lane>>4)<<3) + (lane&7), col8 = (lane>>3)&1
    const uint32_t b_r = ((lane >> 4) << 3) + (lane & 7), b_c8 = ((lane >> 3) & 1) << 3;

    float acc[2][8][4];
#pragma unroll
    for (int mi = 0; mi < 2; ++mi)
#pragma unroll
        for (int ni = 0; ni < 8; ++ni)
#pragma unroll
            for (int r = 0; r < 4; ++r) acc[mi][ni][r] = 0.0f;

    for (int kt = 0; kt < HID; kt += 32) {
        // Load 4 tiles of 128x32 halfs each (8 uint4 per thread)
#pragma unroll
        for (int i = 0; i < 8; ++i) {
            const int tile = i >> 1;                    // constant per unrolled i
            const int rem = ((i & 1) << 8) + t;         // 0..511
            const int row = rem >> 2, q = rem & 3;
            uint4 v = *(const uint4*)(srcs[tile] + (size_t)row * HID + kt + q * 8);
            *(uint4*)(sm + tile * 5120 + row * 40 + q * 8) = v;
        }
        __syncthreads();

#pragma unroll
        for (int ks = 0; ks < 2; ++ks) {
            const uint32_t k0 = ks * 16;
            uint32_t ah[2][4], al[2][4], bh[4][4], bl[4][4];
            // A fragments: 2 m16 tiles (hi & lo)
#pragma unroll
            for (int mi = 0; mi < 2; ++mi) {
                uint32_t off = ((wm + mi * 16 + a_r) * 40 + k0 + a_c8) * 2;
                ldsm4(ah[mi][0], ah[mi][1], ah[mi][2], ah[mi][3], sb + 0 * 10240 + off);
                ldsm4(al[mi][0], al[mi][1], al[mi][2], al[mi][3], sb + 1 * 10240 + off);
            }
            // B fragments: 8 n8 tiles packed as 4 x (x4) (hi & lo)
#pragma unroll
            for (int pi = 0; pi < 4; ++pi) {
                uint32_t off = ((wn + pi * 16 + b_r) * 40 + k0 + b_c8) * 2;
                ldsm4(bh[pi][0], bh[pi][1], bh[pi][2], bh[pi][3], sb + 2 * 10240 + off);
                ldsm4(bl[pi][0], bl[pi][1], bl[pi][2], bl[pi][3], sb + 3 * 10240 + off);
            }
            // 3-term split MMAs
#pragma unroll
            for (int mi = 0; mi < 2; ++mi)
#pragma unroll
                for (int pi = 0; pi < 4; ++pi) {
#pragma unroll
                    for (int half = 0; half < 2; ++half) {
                        const int ni = pi * 2 + half;
                        const uint32_t B0 = bh[pi][half * 2], B1 = bh[pi][half * 2 + 1];
                        const uint32_t C0 = bl[pi][half * 2], C1 = bl[pi][half * 2 + 1];
                        mma16816(acc[mi][ni], ah[mi][0], ah[mi][1], ah[mi][2], ah[mi][3], B0, B1);
                        mma16816(acc[mi][ni], ah[mi][0], ah[mi][1], ah[mi][2], ah[mi][3], C0, C1);
                        mma16816(acc[mi][ni], al[mi][0], al[mi][1], al[mi][2], al[mi][3], B0, B1);
                    }
                }
        }
        __syncthreads();
    }

    // Epilogue: write C fragments
#pragma unroll
    for (int mi = 0; mi < 2; ++mi) {
#pragma unroll
        for (int ni = 0; ni < 8; ++ni) {
            const int col = bn + wn + ni * 8 + 2 * (lane & 3);
            float b0 = 0.f, b1 = 0.f;
            if (MODE < 3) { b0 = bias[col]; b1 = bias[col + 1]; }
#pragma unroll
            for (int rr = 0; rr < 2; ++rr) {
                const int row = bm + wm + mi * 16 + (lane >> 2) + rr * 8;
                float2 v;
                v.x = acc[mi][ni][rr * 2 + 0] + b0;
                v.y = acc[mi][ni][rr * 2 + 1] + b1;
                if (MODE < 3) {
                    const int head = col >> 6, d = col & 63;
                    float* dst = (MODE == 0) ? g_q : (MODE == 1) ? g_k : g_v;
                    *(float2*)(dst + ((size_t)head * S_LEN + row) * HD + d) = v;
                } else {
                    *(float2*)(outp + (size_t)row * HID + col) = v;
                }
            }
        }
    }
}

// ---------------------------------------------------------------------------
// RoPE in-place on g_q (WHICH=0) or g_k (WHICH=1). pairs (j, j+32).
// ---------------------------------------------------------------------------
template <int WHICH>
__global__ __launch_bounds__(256) void rope_k()
{
    const int idx = blockIdx.x * blockDim.x + threadIdx.x;
    const int nheads = (WHICH == 0) ? NH : NKV;
    const int total = nheads * S_LEN * 32;
    if (idx >= total) return;
    const int j = idx & 31;
    const int s = (idx >> 5) & (S_LEN - 1);
    const int h = idx >> 16;

    const float inv_freq = powf(10000.0f, -((float)(2 * j)) / 64.0f);
    const float ang = (float)s * inv_freq;
    float sn, cs;
    sincosf(ang, &sn, &cs);

    float* p = (WHICH == 0 ? g_q : g_k) + ((size_t)h * S_LEN + s) * HD;
    const float x1 = p[j];
    const float x2 = p[j + 32];
    p[j]      = x1 * cs - x2 * sn;
    p[j + 32] = x2 * cs + x1 * sn;
}

// ---------------------------------------------------------------------------
// Flash attention (fp32), epilogue emits bf16 hi/lo ctx split.
// ---------------------------------------------------------------------------
#define ATTN_SMEM ((64 * 64 + 2 * 64 * 65) * 4)

__global__ __launch_bounds__(256) void attn_k()
{
    const int h = blockIdx.y;
    const int zz = blockIdx.x;
    const int qb = (zz & 1) ? (31 - (zz >> 1)) : (zz >> 1);
    const int kvh = h >> 2;

    extern __shared__ float sm[];
    float* Qs = sm;
    float* KP = sm + 64 * 64;
    float* Vs = KP + 64 * 65;

    const int t = threadIdx.x;
    const int tx = t & 15;
    const int ty = t >> 4;
    const int r0 = ty * 4;
    const int c0 = tx * 4;

    const float* Qg = g_q + ((size_t)h * S_LEN + (size_t)qb * 64) * HD;
    for (int i = t; i < 1024; i += 256) {
        const int r = i >> 4;
        const int q = (i & 15) * 4;
        *(float4*)(Qs + r * 64 + q) = *(const float4*)(Qg + r * 64 + q);
    }

    float m_i[4], l_i[4], acc[4][4];
#pragma unroll
    for (int i = 0; i < 4; ++i) {
        m_i[i] = -1e30f; l_i[i] = 0.0f;
#pragma unroll
        for (int j = 0; j < 4; ++j) acc[i][j] = 0.0f;
    }

    for (int kb = 0; kb <= qb; ++kb) {
        __syncthreads();
        const float* Kg = g_k + ((size_t)kvh * S_LEN + (size_t)kb * 64) * HD;
        const float* Vg = g_v + ((size_t)kvh * S_LEN + (size_t)kb * 64) * HD;
        for (int i = t; i < 1024; i += 256) {
            const int r = i >> 4;
            const int q = (i & 15) * 4;
            float4 kk = *(const float4*)(Kg + r * 64 + q);
            KP[r * 65 + q + 0] = kk.x; KP[r * 65 + q + 1] = kk.y;
            KP[r * 65 + q + 2] = kk.z; KP[r * 65 + q + 3] = kk.w;
            float4 vv = *(const float4*)(Vg + r * 64 + q);
            Vs[r * 65 + q + 0] = vv.x; Vs[r * 65 + q + 1] = vv.y;
            Vs[r * 65 + q + 2] = vv.z; Vs[r * 65 + q + 3] = vv.w;
        }
        __syncthreads();

        float s[4][4];
#pragma unroll
        for (int i = 0; i < 4; ++i)
#pragma unroll
            for (int j = 0; j < 4; ++j) s[i][j] = 0.0f;

#pragma unroll 8
        for (int k = 0; k < 64; ++k) {
            float a0 = Qs[(r0 + 0) * 64 + k];
            float a1 = Qs[(r0 + 1) * 64 + k];
            float a2 = Qs[(r0 + 2) * 64 + k];
            float a3 = Qs[(r0 + 3) * 64 + k];
            float b0 = KP[(c0 + 0) * 65 + k];
            float b1 = KP[(c0 + 1) * 65 + k];
            float b2 = KP[(c0 + 2) * 65 + k];
            float b3 = KP[(c0 + 3) * 65 + k];
            s[0][0] += a0 * b0; s[0][1] += a0 * b1; s[0][2] += a0 * b2; s[0][3] += a0 * b3;
            s[1][0] += a1 * b0; s[1][1] += a1 * b1; s[1][2] += a1 * b2; s[1][3] += a1 * b3;
            s[2][0] += a2 * b0; s[2][1] += a2 * b1; s[2][2] += a2 * b2; s[2][3] += a2 * b3;
            s[3][0] += a3 * b0; s[3][1] += a3 * b1; s[3][2] += a3 * b2; s[3][3] += a3 * b3;
        }

        const bool diag = (kb == qb);
        float mt[4];
#pragma unroll
        for (int i = 0; i < 4; ++i) {
#pragma unroll
            for (int j = 0; j < 4; ++j) {
                float v = s[i][j] * 0.125f;
                v = fminf(fmaxf(v, -50.0f), 50.0f);
                if (diag && (c0 + j) > (r0 + i)) v = -1e30f;
                s[i][j] = v;
            }
            mt[i] = fmaxf(fmaxf(s[i][0], s[i][1]), fmaxf(s[i][2], s[i][3]));
        }
#pragma unroll
        for (int o = 1; o < 16; o <<= 1)
#pragma unroll
            for (int i = 0; i < 4; ++i)
                mt[i] = fmaxf(mt[i], __shfl_xor_sync(0xffffffffu, mt[i], o));

        float corr[4], rs[4];
#pragma unroll
        for (int i = 0; i < 4; ++i) {
            const float mn = fmaxf(m_i[i], mt[i]);
            corr[i] = __expf(m_i[i] - mn);
            m_i[i] = mn;
            float r = 0.0f;
#pragma unroll
            for (int j = 0; j < 4; ++j) {
                const float p = __expf(s[i][j] - mn);
                s[i][j] = p;
                r += p;
            }
            rs[i] = r;
        }
#pragma unroll
        for (int o = 1; o < 16; o <<= 1)
#pragma unroll
            for (int i = 0; i < 4; ++i)
                rs[i] += __shfl_xor_sync(0xffffffffu, rs[i], o);
#pragma unroll
        for (int i = 0; i < 4; ++i) {
            l_i[i] = l_i[i] * corr[i] + rs[i];
#pragma unroll
            for (int j = 0; j < 4; ++j) acc[i][j] *= corr[i];
        }

        __syncthreads();
#pragma unroll
        for (int i = 0; i < 4; ++i)
#pragma unroll
            for (int j = 0; j < 4; ++j)
                KP[(r0 + i) * 65 + (c0 + j)] = s[i][j];
        __syncthreads();

#pragma unroll 8
        for (int c = 0; c < 64; ++c) {
            float p0 = KP[(r0 + 0) * 65 + c];
            float p1 = KP[(r0 + 1) * 65 + c];
            float p2 = KP[(r0 + 2) * 65 + c];
            float p3 = KP[(r0 + 3) * 65 + c];
            float v0 = Vs[c * 65 + c0 + 0];
            float v1 = Vs[c * 65 + c0 + 1];
            float v2 = Vs[c * 65 + c0 + 2];
            float v3 = Vs[c * 65 + c0 + 3];
            acc[0][0] += p0 * v0; acc[0][1] += p0 * v1; acc[0][2] += p0 * v2; acc[0][3] += p0 * v3;
            acc[1][0] += p1 * v0; acc[1][1] += p1 * v1; acc[1][2] += p1 * v2; acc[1][3] += p1 * v3;
            acc[2][0] += p2 * v0; acc[2][1] += p2 * v1; acc[2][2] += p2 * v2; acc[2][3] += p2 * v3;
            acc[3][0] += p3 * v0; acc[3][1] += p3 * v1; acc[3][2] += p3 * v2; acc[3][3] += p3 * v3;
        }
    }

#pragma unroll
    for (int i = 0; i < 4; ++i) {
        const float inv = 1.0f / l_i[i];
        const int row = qb * 64 + r0 + i;
        const size_t base = (size_t)row * HID + h * 64 + c0;
#pragma unroll
        for (int j = 0; j < 4; ++j) {
            const float v = acc[i][j] * inv;
            const __nv_bfloat16 hh = __float2bfloat16(v);
            g_Ch[base + j] = hh;
            g_Cl[base + j] = __float2bfloat16(v - __bfloat162float(hh));
        }
    }
}

// ---------------------------------------------------------------------------
// Launcher
// ---------------------------------------------------------------------------
extern "C" void kernel_launch(void* const* d_in, const int* in_sizes, int n_in,
                              void* d_out, int out_size)
{
    const float* X  = (const float*)d_in[0];
    const float* Wq = (const float*)d_in[2];
    const float* bq = (const float*)d_in[3];
    const float* Wk = (const float*)d_in[4];
    const float* bk = (const float*)d_in[5];
    const float* Wv = (const float*)d_in[6];
    const float* bv = (const float*)d_in[7];
    const float* Wo = (const float*)d_in[8];
    float* out = (float*)d_out;

    // Split fp32 -> bf16 hi/lo
    split_k<<<(S_LEN * HID / 4 + 255) / 256, 256>>>(X,  0, S_LEN * HID / 4);
    split_k<<<(HID * HID / 4 + 255) / 256, 256>>>(Wq, 1, HID * HID / 4);
    split_k<<<(NKV * HD * HID / 4 + 255) / 256, 256>>>(Wk, 2, NKV * HD * HID / 4);
    split_k<<<(NKV * HD * HID / 4 + 255) / 256, 256>>>(Wv, 3, NKV * HD * HID / 4);
    split_k<<<(HID * HID / 4 + 255) / 256, 256>>>(Wo, 4, HID * HID / 4);

    // HMMA projections
    hgemm_k<0><<<dim3(HID / 128, S_LEN / 128), 256>>>(bq, nullptr);
    hgemm_k<1><<<dim3((NKV * HD) / 128, S_LEN / 128), 256>>>(bk, nullptr);
    hgemm_k<2><<<dim3((NKV * HD) / 128, S_LEN / 128), 256>>>(bv, nullptr);

    // RoPE
    rope_k<0><<<(NH * S_LEN * 32) / 256, 256>>>();
    rope_k<1><<<(NKV * S_LEN * 32) / 256, 256>>>();

    // Flash attention (fp32), emits ctx hi/lo split
    cudaFuncSetAttribute(attn_k, cudaFuncAttributeMaxDynamicSharedMemorySize, ATTN_SMEM);
    attn_k<<<dim3(32, NH), 256, ATTN_SMEM>>>();

    // Output projection
    hgemm_k<3><<<dim3(HID / 128, S_LEN / 128), 256>>>(nullptr, out);
}

// round 4
// speedup vs baseline: 2.9233x; 1.6042x over previous
#include <cuda_runtime.h>
#include <cuda_bf16.h>
#include <math.h>
#include <stdint.h>

#define S_LEN 2048
#define HID   2048
#define NH    32
#define NKV   8
#define HD    64

// ---------------------------------------------------------------------------
// Scratch (device globals)
// ---------------------------------------------------------------------------
__device__ float g_q[NH * S_LEN * HD];     // pre-RoPE Q fp32
__device__ float g_k[NKV * S_LEN * HD];    // pre-RoPE K fp32

__device__ __nv_bfloat16 g_Xh[S_LEN * HID],  g_Xl[S_LEN * HID];
__device__ __nv_bfloat16 g_Wqh[HID * HID],   g_Wql[HID * HID];
__device__ __nv_bfloat16 g_Wkh[NKV*HD*HID],  g_Wkl[NKV*HD*HID];
__device__ __nv_bfloat16 g_Wvh[NKV*HD*HID],  g_Wvl[NKV*HD*HID];
__device__ __nv_bfloat16 g_Woh[HID * HID],   g_Wol[HID * HID];
__device__ __nv_bfloat16 g_Ch[S_LEN * HID],  g_Cl[S_LEN * HID];    // attn out split

__device__ __nv_bfloat16 g_qh[NH * S_LEN * HD],  g_ql[NH * S_LEN * HD];   // post-RoPE
__device__ __nv_bfloat16 g_kh[NKV * S_LEN * HD], g_kl[NKV * S_LEN * HD];
__device__ __nv_bfloat16 g_vh[NKV * S_LEN * HD], g_vl[NKV * S_LEN * HD];

// ---------------------------------------------------------------------------
// PTX helpers (plain sm_80+ features only — no 'a'-gated instructions)
// ---------------------------------------------------------------------------
__device__ __forceinline__ uint32_t s2u(const void* p) {
    uint32_t a;
    asm("{ .reg .u64 t; cvta.to.shared.u64 t, %1; cvt.u32.u64 %0, t; }" : "=r"(a) : "l"(p));
    return a;
}

__device__ __forceinline__ void ldsm4(uint32_t* r, uint32_t addr) {
    asm volatile("ldmatrix.sync.aligned.m8n8.x4.shared.b16 {%0,%1,%2,%3}, [%4];"
                 : "=r"(r[0]), "=r"(r[1]), "=r"(r[2]), "=r"(r[3]) : "r"(addr));
}

__device__ __forceinline__ void ldsm4t(uint32_t* r, uint32_t addr) {
    asm volatile("ldmatrix.sync.aligned.m8n8.x4.trans.shared.b16 {%0,%1,%2,%3}, [%4];"
                 : "=r"(r[0]), "=r"(r[1]), "=r"(r[2]), "=r"(r[3]) : "r"(addr));
}

__device__ __forceinline__ void mma16816(float* d, uint32_t a0, uint32_t a1, uint32_t a2,
                                         uint32_t a3, uint32_t b0, uint32_t b1) {
    asm volatile(
        "mma.sync.aligned.m16n8k16.row.col.f32.bf16.bf16.f32 "
        "{%0,%1,%2,%3}, {%4,%5,%6,%7}, {%8,%9}, {%0,%1,%2,%3};"
        : "+f"(d[0]), "+f"(d[1]), "+f"(d[2]), "+f"(d[3])
        : "r"(a0), "r"(a1), "r"(a2), "r"(a3), "r"(b0), "r"(b1));
}

// pack two fp32 -> bf16x2 {lo: first, hi: second}
__device__ __forceinline__ uint32_t packbf(float lo, float hi) {
    uint32_t r;
    asm("cvt.rn.bf16x2.f32 %0, %1, %2;" : "=r"(r) : "f"(hi), "f"(lo));
    return r;
}
__device__ __forceinline__ float lo_of(uint32_t p) { return __uint_as_float(p << 16); }
__device__ __forceinline__ float hi_of(uint32_t p) { return __uint_as_float(p & 0xFFFF0000u); }

// ---------------------------------------------------------------------------
// fp32 -> (bf16 hi, bf16 lo) split
// ---------------------------------------------------------------------------
__global__ __launch_bounds__(256) void split_k(const float* __restrict__ src, int which, int n4)
{
    int i = blockIdx.x * 256 + threadIdx.x;
    if (i >= n4) return;
    __nv_bfloat16 *hi, *lo;
    switch (which) {
        case 0: hi = g_Xh;  lo = g_Xl;  break;
        case 1: hi = g_Wqh; lo = g_Wql; break;
        case 2: hi = g_Wkh; lo = g_Wkl; break;
        case 3: hi = g_Wvh; lo = g_Wvl; break;
        default: hi = g_Woh; lo = g_Wol; break;
    }
    float4 v = ((const float4*)src)[i];
    __nv_bfloat16 h[4], l[4];
    float f[4] = {v.x, v.y, v.z, v.w};
#pragma unroll
    for (int k = 0; k < 4; ++k) {
        h[k] = __float2bfloat16(f[k]);
        l[k] = __float2bfloat16(f[k] - __bfloat162float(h[k]));
    }
    *(uint64_t*)(hi + 4 * i) = *(uint64_t*)h;
    *(uint64_t*)(lo + 4 * i) = *(uint64_t*)l;
}

// ---------------------------------------------------------------------------
// Split-bf16 HMMA GEMM (validated round-3 structure).
// MODE 0/1 -> fp32 g_q/g_k; MODE 2 -> bf16 split g_vh/g_vl; MODE 3 -> out.
// ---------------------------------------------------------------------------
template <int MODE>
__global__ __launch_bounds__(256) void hgemm_k(const float* __restrict__ bias,
                                               float* __restrict__ outp)
{
    __shared__ __align__(16) __nv_bfloat16 sm[4 * 128 * 40];

    const int t = threadIdx.x, w = t >> 5, lane = t & 31;
    const int bm = blockIdx.y * 128, bn = blockIdx.x * 128;
    const int wm = (w & 3) * 32, wn = (w >> 2) * 64;

    const __nv_bfloat16 *Ah, *Al, *Bh, *Bl;
    if (MODE == 0)      { Ah = g_Xh; Al = g_Xl; Bh = g_Wqh; Bl = g_Wql; }
    else if (MODE == 1) { Ah = g_Xh; Al = g_Xl; Bh = g_Wkh; Bl = g_Wkl; }
    else if (MODE == 2) { Ah = g_Xh; Al = g_Xl; Bh = g_Wvh; Bl = g_Wvl; }
    else                { Ah = g_Ch; Al = g_Cl; Bh = g_Woh; Bl = g_Wol; }

    const __nv_bfloat16* srcs[4] = { Ah + (size_t)bm * HID, Al + (size_t)bm * HID,
                                     Bh + (size_t)bn * HID, Bl + (size_t)bn * HID };

    const uint32_t sb = s2u(sm);
    const uint32_t a_r = lane & 15, a_c8 = (lane >> 4) << 3;
    const uint32_t b_r = ((lane >> 4) << 3) + (lane & 7), b_c8 = ((lane >> 3) & 1) << 3;

    float acc[2][8][4];
#pragma unroll
    for (int mi = 0; mi < 2; ++mi)
#pragma unroll
        for (int ni = 0; ni < 8; ++ni)
#pragma unroll
            for (int r = 0; r < 4; ++r) acc[mi][ni][r] = 0.0f;

    for (int kt = 0; kt < HID; kt += 32) {
#pragma unroll
        for (int i = 0; i < 8; ++i) {
            const int tile = i >> 1;
            const int rem = ((i & 1) << 8) + t;
            const int row = rem >> 2, q = rem & 3;
            uint4 v = *(const uint4*)(srcs[tile] + (size_t)row * HID + kt + q * 8);
            *(uint4*)(sm + tile * 5120 + row * 40 + q * 8) = v;
        }
        __syncthreads();

#pragma unroll
        for (int ks = 0; ks < 2; ++ks) {
            const uint32_t k0 = ks * 16;
            uint32_t ah[2][4], al[2][4], bh[4][4], bl[4][4];
#pragma unroll
            for (int mi = 0; mi < 2; ++mi) {
                uint32_t off = ((wm + mi * 16 + a_r) * 40 + k0 + a_c8) * 2;
                ldsm4(ah[mi], sb + 0 * 10240 + off);
                ldsm4(al[mi], sb + 1 * 10240 + off);
            }
#pragma unroll
            for (int pi = 0; pi < 4; ++pi) {
                uint32_t off = ((wn + pi * 16 + b_r) * 40 + k0 + b_c8) * 2;
                ldsm4(bh[pi], sb + 2 * 10240 + off);
                ldsm4(bl[pi], sb + 3 * 10240 + off);
            }
#pragma unroll
            for (int mi = 0; mi < 2; ++mi)
#pragma unroll
                for (int pi = 0; pi < 4; ++pi) {
#pragma unroll
                    for (int half = 0; half < 2; ++half) {
                        const int ni = pi * 2 + half;
                        const uint32_t B0 = bh[pi][half * 2], B1 = bh[pi][half * 2 + 1];
                        const uint32_t C0 = bl[pi][half * 2], C1 = bl[pi][half * 2 + 1];
                        mma16816(acc[mi][ni], ah[mi][0], ah[mi][1], ah[mi][2], ah[mi][3], B0, B1);
                        mma16816(acc[mi][ni], ah[mi][0], ah[mi][1], ah[mi][2], ah[mi][3], C0, C1);
                        mma16816(acc[mi][ni], al[mi][0], al[mi][1], al[mi][2], al[mi][3], B0, B1);
                    }
                }
        }
        __syncthreads();
    }

#pragma unroll
    for (int mi = 0; mi < 2; ++mi) {
#pragma unroll
        for (int ni = 0; ni < 8; ++ni) {
            const int col = bn + wn + ni * 8 + 2 * (lane & 3);
            float b0 = 0.f, b1 = 0.f;
            if (MODE < 3) { b0 = bias[col]; b1 = bias[col + 1]; }
#pragma unroll
            for (int rr = 0; rr < 2; ++rr) {
                const int row = bm + wm + mi * 16 + (lane >> 2) + rr * 8;
                float vx = acc[mi][ni][rr * 2 + 0] + b0;
                float vy = acc[mi][ni][rr * 2 + 1] + b1;
                if (MODE == 0 || MODE == 1) {
                    const int head = col >> 6, d = col & 63;
                    float* dst = (MODE == 0) ? g_q : g_k;
                    float2 v2 = {vx, vy};
                    *(float2*)(dst + ((size_t)head * S_LEN + row) * HD + d) = v2;
                } else if (MODE == 2) {
                    const int head = col >> 6, d = col & 63;
                    uint32_t ph = packbf(vx, vy);
                    uint32_t pl = packbf(vx - lo_of(ph), vy - hi_of(ph));
                    const size_t off = ((size_t)head * S_LEN + row) * HD + d;
                    *(uint32_t*)(g_vh + off) = ph;
                    *(uint32_t*)(g_vl + off) = pl;
                } else {
                    float2 v2 = {vx, vy};
                    *(float2*)(outp + (size_t)row * HID + col) = v2;
                }
            }
        }
    }
}

// ---------------------------------------------------------------------------
// RoPE: read fp32 g_q/g_k, write bf16 hi/lo splits. Thread covers 2 pairs
// (j2, j2+1) and (j2+32, j2+33) -> 4-byte packed stores.
// ---------------------------------------------------------------------------
template <int WHICH>
__global__ __launch_bounds__(256) void rope_k()
{
    const int idx = blockIdx.x * 256 + threadIdx.x;
    const int nheads = (WHICH == 0) ? NH : NKV;
    if (idx >= nheads * S_LEN * 16) return;
    const int j2 = (idx & 15) * 2;
    const int s = (idx >> 4) & (S_LEN - 1);
    const int h = idx >> 15;

    const float* src = (WHICH == 0 ? g_q : g_k) + ((size_t)h * S_LEN + s) * HD;
    float y1[2], y2[2];
#pragma unroll
    for (int e = 0; e < 2; ++e) {
        const int j = j2 + e;
        const float inv_freq = powf(10000.0f, -((float)(2 * j)) / 64.0f);
        float sn, cs;
        sincosf((float)s * inv_freq, &sn, &cs);
        const float x1 = src[j], x2 = src[j + 32];
        y1[e] = x1 * cs - x2 * sn;
        y2[e] = x2 * cs + x1 * sn;
    }
    __nv_bfloat16* dh = (WHICH == 0 ? g_qh : g_kh) + ((size_t)h * S_LEN + s) * HD;
    __nv_bfloat16* dl = (WHICH == 0 ? g_ql : g_kl) + ((size_t)h * S_LEN + s) * HD;
    uint32_t p1 = packbf(y1[0], y1[1]);
    uint32_t p2 = packbf(y2[0], y2[1]);
    *(uint32_t*)(dh + j2) = p1;
    *(uint32_t*)(dh + j2 + 32) = p2;
    *(uint32_t*)(dl + j2) = packbf(y1[0] - lo_of(p1), y1[1] - hi_of(p1));
    *(uint32_t*)(dl + j2 + 32) = packbf(y2[0] - lo_of(p2), y2[1] - hi_of(p2));
}

// ---------------------------------------------------------------------------
// HMMA flash attention. CTA = (head, 64 q-rows), 4 warps x 16 rows.
// 3-term bf16 splits for QK^T and PV. smem stride 72 halfs (conflict-free LDSM).
// ---------------------------------------------------------------------------
#define TILE_B 9216                       // 64*72*2 bytes per tile
#define ATTN_SMEM (6 * TILE_B)            // Qh Ql Kh Kl Vh Vl = 55296 B

__global__ __launch_bounds__(128) void attn_k()
{
    extern __shared__ __nv_bfloat16 smb[];
    const uint32_t sb = s2u(smb);
    const int h = blockIdx.y;
    const int zz = blockIdx.x;
    const int qb = (zz & 1) ? (31 - (zz >> 1)) : (zz >> 1);
    const int kvh = h >> 2;

    const int t = threadIdx.x, w = t >> 5, lane = t & 31;

    // byte offsets of the 6 tiles
    const uint32_t QHB = 0, QLB = TILE_B, KHB = 2*TILE_B, KLB = 3*TILE_B,
                   VHB = 4*TILE_B, VLB = 5*TILE_B;

    // ---- load Q tiles ----
    {
        const __nv_bfloat16* qh = g_qh + ((size_t)h * S_LEN + (size_t)qb * 64) * HD;
        const __nv_bfloat16* ql = g_ql + ((size_t)h * S_LEN + (size_t)qb * 64) * HD;
#pragma unroll
        for (int ii = 0; ii < 4; ++ii) {
            const int i = ii * 128 + t;
            const int row = i >> 3, ch = i & 7;
            *(uint4*)((char*)smb + QHB + (row * 72 + ch * 8) * 2) =
                *(const uint4*)(qh + row * 64 + ch * 8);
            *(uint4*)((char*)smb + QLB + (row * 72 + ch * 8) * 2) =
                *(const uint4*)(ql + row * 64 + ch * 8);
        }
    }
    __syncthreads();

    // ---- Q fragments (register-resident) ----
    const uint32_t a_r = lane & 15, a_c8 = (lane >> 4) << 3;
    const uint32_t b_r = ((lane >> 4) << 3) + (lane & 7), b_c8 = ((lane >> 3) & 1) << 3;
    uint32_t qfh[4][4], qfl[4][4];
#pragma unroll
    for (int ks = 0; ks < 4; ++ks) {
        uint32_t off = ((w * 16 + a_r) * 72 + ks * 16 + a_c8) * 2;
        ldsm4(qfh[ks], sb + QHB + off);
        ldsm4(qfl[ks], sb + QLB + off);
    }

    float oacc[8][4];
#pragma unroll
    for (int nt = 0; nt < 8; ++nt)
#pragma unroll
        for (int e = 0; e < 4; ++e) oacc[nt][e] = 0.0f;
    float m_i[2] = {-1e30f, -1e30f}, l_i[2] = {0.0f, 0.0f};

    const int grow0 = qb * 64 + w * 16 + (lane >> 2);   // row of e=0,1; +8 for e=2,3

    for (int kb = 0; kb <= qb; ++kb) {
        __syncthreads();   // prior-iteration LDSM done before overwrite
        {
            const size_t base = ((size_t)kvh * S_LEN + (size_t)kb * 64) * HD;
            const __nv_bfloat16* srcs[4] = { g_kh + base, g_kl + base, g_vh + base, g_vl + base };
            const uint32_t dstb[4] = { KHB, KLB, VHB, VLB };
#pragma unroll
            for (int ii = 0; ii < 16; ++ii) {
                const int tile = ii >> 2;
                const int rem = (ii & 3) * 128 + t;
                const int row = rem >> 3, ch = rem & 7;
                *(uint4*)((char*)smb + dstb[tile] + (row * 72 + ch * 8) * 2) =
                    *(const uint4*)(srcs[tile] + row * 64 + ch * 8);
            }
        }
        __syncthreads();

        // ---- S = Q K^T (3-term) ----
        float sacc[8][4];
#pragma unroll
        for (int nt = 0; nt < 8; ++nt)
#pragma unroll
            for (int e = 0; e < 4; ++e) sacc[nt][e] = 0.0f;

#pragma unroll
        for (int ks = 0; ks < 4; ++ks) {
#pragma unroll
            for (int np = 0; np < 4; ++np) {
                uint32_t BH[4], BL[4];
                uint32_t off = ((np * 16 + b_r) * 72 + ks * 16 + b_c8) * 2;
                ldsm4(BH, sb + KHB + off);
                ldsm4(BL, sb + KLB + off);
#pragma unroll
                for (int half = 0; half < 2; ++half) {
                    const int nt = np * 2 + half;
                    mma16816(sacc[nt], qfh[ks][0], qfh[ks][1], qfh[ks][2], qfh[ks][3],
                             BH[half * 2], BH[half * 2 + 1]);
                    mma16816(sacc[nt], qfh[ks][0], qfh[ks][1], qfh[ks][2], qfh[ks][3],
                             BL[half * 2], BL[half * 2 + 1]);
                    mma16816(sacc[nt], qfl[ks][0], qfl[ks][1], qfl[ks][2], qfl[ks][3],
                             BH[half * 2], BH[half * 2 + 1]);
                }
            }
        }

        // ---- softmax (online) ----
        const bool diag = (kb == qb);
        float mt[2] = {-1e30f, -1e30f};
#pragma unroll
        for (int nt = 0; nt < 8; ++nt) {
#pragma unroll
            for (int e = 0; e < 4; ++e) {
                float v = sacc[nt][e] * 0.125f;
                v = fminf(fmaxf(v, -50.0f), 50.0f);
                if (diag) {
                    const int col = kb * 64 + nt * 8 + 2 * (lane & 3) + (e & 1);
                    const int row = grow0 + (e >> 1) * 8;
                    if (col > row) v = -1e30f;
                }
                sacc[nt][e] = v;
                mt[e >> 1] = fmaxf(mt[e >> 1], v);
            }
        }
#pragma unroll
        for (int o = 1; o < 4; o <<= 1) {
            mt[0] = fmaxf(mt[0], __shfl_xor_sync(0xffffffffu, mt[0], o));
            mt[1] = fmaxf(mt[1], __shfl_xor_sync(0xffffffffu, mt[1], o));
        }
        float corr[2], rs[2] = {0.0f, 0.0f};
#pragma unroll
        for (int rr = 0; rr < 2; ++rr) {
            const float mn = fmaxf(m_i[rr], mt[rr]);
            corr[rr] = __expf(m_i[rr] - mn);
            m_i[rr] = mn;
        }
#pragma unroll
        for (int nt = 0; nt < 8; ++nt)
#pragma unroll
            for (int e = 0; e < 4; ++e) {
                const float p = __expf(sacc[nt][e] - m_i[e >> 1]);
                sacc[nt][e] = p;
                rs[e >> 1] += p;
            }
#pragma unroll
        for (int o = 1; o < 4; o <<= 1) {
            rs[0] += __shfl_xor_sync(0xffffffffu, rs[0], o);
            rs[1] += __shfl_xor_sync(0xffffffffu, rs[1], o);
        }
#pragma unroll
        for (int rr = 0; rr < 2; ++rr) l_i[rr] = l_i[rr] * corr[rr] + rs[rr];
#pragma unroll
        for (int nt = 0; nt < 8; ++nt)
#pragma unroll
            for (int e = 0; e < 4; ++e) oacc[nt][e] *= corr[e >> 1];

        // ---- O += P V (3-term; P frags from accumulators) ----
#pragma unroll
        for (int ks = 0; ks < 4; ++ks) {
            const int L = 2 * ks, R = 2 * ks + 1;
            uint32_t ph[4], pl[4];
            ph[0] = packbf(sacc[L][0], sacc[L][1]);
            ph[1] = packbf(sacc[L][2], sacc[L][3]);
            ph[2] = packbf(sacc[R][0], sacc[R][1]);
            ph[3] = packbf(sacc[R][2], sacc[R][3]);
            pl[0] = packbf(sacc[L][0] - lo_of(ph[0]), sacc[L][1] - hi_of(ph[0]));
            pl[1] = packbf(sacc[L][2] - lo_of(ph[1]), sacc[L][3] - hi_of(ph[1]));
            pl[2] = packbf(sacc[R][0] - lo_of(ph[2]), sacc[R][1] - hi_of(ph[2]));
            pl[3] = packbf(sacc[R][2] - lo_of(ph[3]), sacc[R][3] - hi_of(ph[3]));
#pragma unroll
            for (int dp = 0; dp < 4; ++dp) {
                uint32_t VH4[4], VL4[4];
                uint32_t voff = ((ks * 16 + (lane & 7) + ((lane >> 3) & 1) * 8) * 72
                                 + dp * 16 + ((lane >> 4) << 3)) * 2;
                ldsm4t(VH4, sb + VHB + voff);
                ldsm4t(VL4, sb + VLB + voff);
#pragma unroll
                for (int half = 0; half < 2; ++half) {
                    const int nt = dp * 2 + half;
                    mma16816(oacc[nt], ph[0], ph[1], ph[2], ph[3],
                             VH4[half * 2], VH4[half * 2 + 1]);
                    mma16816(oacc[nt], ph[0], ph[1], ph[2], ph[3],
                             VL4[half * 2], VL4[half * 2 + 1]);
                    mma16816(oacc[nt], pl[0], pl[1], pl[2], pl[3],
                             VH4[half * 2], VH4[half * 2 + 1]);
                }
            }
        }
    }

    // ---- epilogue: normalize, split, store ----
    const float inv0 = 1.0f / l_i[0], inv1 = 1.0f / l_i[1];
#pragma unroll
    for (int nt = 0; nt < 8; ++nt) {
#pragma unroll
        for (int rr = 0; rr < 2; ++rr) {
            const float inv = rr ? inv1 : inv0;
            const float v0 = oacc[nt][rr * 2 + 0] * inv;
            const float v1 = oacc[nt][rr * 2 + 1] * inv;
            const int srow = qb * 64 + w * 16 + (lane >> 2) + rr * 8;
            const int col = h * 64 + nt * 8 + 2 * (lane & 3);
            uint32_t ph = packbf(v0, v1);
            uint32_t pl = packbf(v0 - lo_of(ph), v1 - hi_of(ph));
            *(uint32_t*)(g_Ch + (size_t)srow * HID + col) = ph;
            *(uint32_t*)(g_Cl + (size_t)srow * HID + col) = pl;
        }
    }
}

// ---------------------------------------------------------------------------
// Launcher
// ---------------------------------------------------------------------------
extern "C" void kernel_launch(void* const* d_in, const int* in_sizes, int n_in,
                              void* d_out, int out_size)
{
    const float* X  = (const float*)d_in[0];
    const float* Wq = (const float*)d_in[2];
    const float* bq = (const float*)d_in[3];
    const float* Wk = (const float*)d_in[4];
    const float* bk = (const float*)d_in[5];
    const float* Wv = (const float*)d_in[6];
    const float* bv = (const float*)d_in[7];
    const float* Wo = (const float*)d_in[8];
    float* out = (float*)d_out;

    split_k<<<(S_LEN * HID / 4 + 255) / 256, 256>>>(X,  0, S_LEN * HID / 4);
    split_k<<<(HID * HID / 4 + 255) / 256, 256>>>(Wq, 1, HID * HID / 4);
    split_k<<<(NKV * HD * HID / 4 + 255) / 256, 256>>>(Wk, 2, NKV * HD * HID / 4);
    split_k<<<(NKV * HD * HID / 4 + 255) / 256, 256>>>(Wv, 3, NKV * HD * HID / 4);
    split_k<<<(HID * HID / 4 + 255) / 256, 256>>>(Wo, 4, HID * HID / 4);

    hgemm_k<0><<<dim3(HID / 128, S_LEN / 128), 256>>>(bq, nullptr);
    hgemm_k<1><<<dim3((NKV * HD) / 128, S_LEN / 128), 256>>>(bk, nullptr);
    hgemm_k<2><<<dim3((NKV * HD) / 128, S_LEN / 128), 256>>>(bv, nullptr);

    rope_k<0><<<(NH * S_LEN * 16) / 256, 256>>>();
    rope_k<1><<<(NKV * S_LEN * 16) / 256, 256>>>();

    cudaFuncSetAttribute(attn_k, cudaFuncAttributeMaxDynamicSharedMemorySize, ATTN_SMEM);
    attn_k<<<dim3(32, NH), 128, ATTN_SMEM>>>();

    hgemm_k<3><<<dim3(HID / 128, S_LEN / 128), 256>>>(nullptr, out);
}